// round 15
// baseline (speedup 1.0000x reference)
#include <cuda_runtime.h>
#include <cuda_fp16.h>
#include <cstdint>

#define N_    16
#define CIN_  512
#define COUT_ 512
#define STY_  512
#define H_    64
#define W_    64
#define HW_   (H_*W_)
#define QW_   66
#define QTOT_ (QW_*QW_)          /* 4356 padded pixels per image */

// ---------------- static device scratch (no allocation allowed) -------------
__device__ float    g_s[N_*CIN_];                    // style modulation
__device__ float    g_wsum2[CIN_*COUT_];             // [ci][co] sum_k w^2
__device__ float    g_demod[N_*COUT_];               // demod scale
__device__ uint32_t g_whf[9*COUT_*CIN_/2];           // fragment-ordered fp16x2 weights
__device__ uint32_t g_xh2[(size_t)N_*QTOT_*CIN_/2];  // [n][q][ci] fp16, premul (u32 view)

// ---------------- helpers ---------------------------------------------------
__device__ __forceinline__ uint32_t smem_u32(const void* p) {
    uint32_t a;
    asm("{ .reg .u64 t; cvta.to.shared.u64 t, %1; cvt.u32.u64 %0, t; }"
        : "=r"(a) : "l"(p));
    return a;
}
__device__ __forceinline__ void cp16(uint32_t dst, const void* src) {
    asm volatile("cp.async.cg.shared.global [%0], [%1], 16;"
                 :: "r"(dst), "l"(src) : "memory");
}
#define CP_COMMIT() asm volatile("cp.async.commit_group;" ::: "memory")
#define CP_WAIT1()  asm volatile("cp.async.wait_group 1;" ::: "memory")

__device__ __forceinline__ void ldsm4(uint32_t* r, uint32_t addr) {
    asm volatile("ldmatrix.sync.aligned.m8n8.x4.shared.b16 {%0,%1,%2,%3}, [%4];"
        : "=r"(r[0]), "=r"(r[1]), "=r"(r[2]), "=r"(r[3]) : "r"(addr));
}
__device__ __forceinline__ void mma_f16(float* d, const uint32_t* a, const uint32_t* b) {
    asm volatile("mma.sync.aligned.m16n8k16.row.col.f32.f16.f16.f32 "
        "{%0,%1,%2,%3}, {%4,%5,%6,%7}, {%8,%9}, {%0,%1,%2,%3};"
        : "+f"(d[0]), "+f"(d[1]), "+f"(d[2]), "+f"(d[3])
        : "r"(a[0]), "r"(a[1]), "r"(a[2]), "r"(a[3]), "r"(b[0]), "r"(b[1]));
}

// ---------------------------------------------------------------------------
// 1) s[n][ci] = style[n] . style_w[ci] + style_b[ci]
// ---------------------------------------------------------------------------
__global__ void style_kernel(const float* __restrict__ style,
                             const float* __restrict__ style_w,
                             const float* __restrict__ style_b) {
    __shared__ float ssty[STY_];
    int n = blockIdx.x;
    int ci = threadIdx.x;
    ssty[ci] = style[n*STY_ + ci];
    __syncthreads();
    const float* wr = style_w + ci*STY_;
    float acc = 0.f;
    #pragma unroll 8
    for (int k = 0; k < STY_; k++) acc += ssty[k] * wr[k];
    g_s[n*CIN_ + ci] = acc + style_b[ci];
}

// ---------------------------------------------------------------------------
// 2) wsum2[ci][co] = sum_k weight[co][ci][k]^2
// ---------------------------------------------------------------------------
__global__ void wsum2_kernel(const float* __restrict__ weight) {
    int idx = blockIdx.x*blockDim.x + threadIdx.x;
    if (idx >= COUT_*CIN_) return;
    int co = idx / CIN_, ci = idx % CIN_;
    const float* w = weight + (size_t)idx*9;
    float a = 0.f;
    #pragma unroll
    for (int k = 0; k < 9; k++) { float v = w[k]; a += v*v; }
    g_wsum2[ci*COUT_ + co] = a;
}

// ---------------------------------------------------------------------------
// 3) demod[n][co] = rsqrt( sum_ci s^2 * wsum2 + eps ) — split-K block reduce
// ---------------------------------------------------------------------------
__global__ void demod_kernel() {
    __shared__ float red[256];
    int n = blockIdx.x, cb = blockIdx.y;
    int co_l = threadIdx.x & 63, g = threadIdx.x >> 6;
    int co = cb*64 + co_l;
    const float* sp = g_s + n*CIN_;
    float acc = 0.f;
    #pragma unroll 16
    for (int ci = g*128; ci < g*128 + 128; ci++) {
        float s = sp[ci];
        acc += s*s*g_wsum2[ci*COUT_ + co];
    }
    red[threadIdx.x] = acc;
    __syncthreads();
    if (g == 0) {
        float t = red[co_l] + red[64+co_l] + red[128+co_l] + red[192+co_l] + 1e-8f;
        g_demod[n*COUT_ + co] = rsqrtf(t);
    }
}

// ---------------------------------------------------------------------------
// 4) weight repack -> fp16x2 in exact m16n8k16 A-fragment order (unchanged R14)
// ---------------------------------------------------------------------------
__global__ void pack_w_kernel(const float* __restrict__ w) {
    int u = blockIdx.x*256 + threadIdx.x;
    if (u >= 9*COUT_*CIN_/2) return;
    int e     = u & 3;
    int lane  = (u >> 2) & 31;
    int mtile = (u >> 7) & 7;
    int ks    = (u >> 10) & 1;
    int chunk = (u >> 11) & 15;
    int cs    = (u >> 15) & 3;
    int k     = u >> 17;
    int g = lane >> 2, t = lane & 3;
    int ci = chunk*32 + ks*16 + 2*t + ((e >> 1) << 3);
    int co = cs*128 + mtile*16 + g + ((e & 1) << 3);
    float v0 = w[((size_t)co*CIN_ + ci)*9 + k];
    float v1 = w[((size_t)co*CIN_ + ci + 1)*9 + k];
    half2 h = __floats2half2_rn(v0, v1);
    g_whf[u] = *(uint32_t*)&h;
}

// ---------------------------------------------------------------------------
// 5) zero padded-border rows of g_xh2 (interior rewritten by pack_x)
// ---------------------------------------------------------------------------
__global__ void zero_border_kernel() {
    int b = blockIdx.x;                     // n*QTOT + q
    int q = b % QTOT_;
    int y = q / QW_, xx = q % QW_;
    if (y != 0 && y != QW_-1 && xx != 0 && xx != QW_-1) return;
    uint4 z = make_uint4(0,0,0,0);
    ((uint4*)(g_xh2 + (size_t)b*256))[threadIdx.x] = z;  // 64 thr x 16B = 1KB
}

// ---------------------------------------------------------------------------
// 6) pack_x: transpose + premultiply + fp16 into [n][q][ci]
//    block: 64 ci x 64 px tile at row y; smem pad 66 halves/row (bank-safe)
// ---------------------------------------------------------------------------
__global__ void pack_x_kernel(const float* __restrict__ x) {
    __shared__ half tp[64*66];              // [px][ci_local]
    __shared__ float ss[64];
    int ci0 = blockIdx.x*64, y = blockIdx.y, n = blockIdx.z;
    int tid = threadIdx.x;
    if (tid < 64) ss[tid] = g_s[n*CIN_ + ci0 + tid];
    __syncthreads();
    #pragma unroll
    for (int it = 0; it < 16; it++) {
        int idx = tid + it*256;             // 64ci x 64px
        int cl = idx >> 6, px = idx & 63;
        float v = x[(((size_t)n*CIN_ + ci0 + cl)*H_ + y)*W_ + px] * ss[cl];
        tp[px*66 + cl] = __float2half_rn(v);
    }
    __syncthreads();
    int w = tid >> 5, lane = tid & 31;
    #pragma unroll
    for (int p = 0; p < 8; p++) {
        int px = w + p*8;
        uint32_t v = *(const uint32_t*)&tp[px*66 + 2*lane];
        int q = (y+1)*QW_ + px + 1;
        g_xh2[((size_t)n*QTOT_ + q)*256 + (ci0 >> 1) + lane] = v;
    }
}

// ---------------------------------------------------------------------------
// 7) conv: mma.sync fp16 m16n8k16, B via ldmatrix.x4 on [q][ci] slab
//    CTA 128co x 128px (2 rows), 8 warps (2m x 4n), warp tile 64x32.
// ---------------------------------------------------------------------------
#define B_ROWB  80                         /* bytes per q row (64 data + 16 pad) */
#define A_BYTES 8192
#define B_BYTES (264*B_ROWB)               /* 21120 */
#define B_OFF   (2*A_BYTES)                /* 16384 */
#define SMEM_TOTAL (2*A_BYTES + 2*B_BYTES) /* 58624 */

__device__ __forceinline__ void load_A_tile(uint32_t dst, const uint32_t* gsrc, int tid) {
    #pragma unroll
    for (int i = 0; i < 2; i++) {
        int f = tid + i*256;                    // 0..511 16B chunks
        cp16(dst + (uint32_t)f*16, gsrc + (size_t)f*4);
    }
}
// src: u32 base at (q0*256 + chunk*16); 264 rows x 4 chunks of 16B
__device__ __forceinline__ void load_B_slab(uint32_t dst, const uint32_t* gsrc, int tid) {
    #pragma unroll
    for (int i = 0; i < 5; i++) {
        int f = tid + i*256;
        if (f < 1056) {
            int row = f >> 2, c = f & 3;
            cp16(dst + (uint32_t)(row*B_ROWB + c*16), gsrc + (size_t)row*256 + c*4);
        }
    }
}

__global__ __launch_bounds__(256, 2)
void conv_mma_kernel(const float* __restrict__ noise,
                     const float* __restrict__ noise_w,
                     float* __restrict__ out) {
    extern __shared__ char smem[];
    const uint32_t sb = smem_u32(smem);
    const int tid  = threadIdx.x;
    const int wid  = tid >> 5;
    const int lane = tid & 31;
    const int g    = lane >> 2;
    const int t    = lane & 3;
    const int warp_m = wid & 1;
    const int warp_n = wid >> 1;
    const int co0 = blockIdx.x * 128;
    const int y0  = blockIdx.y * 2;
    const int n   = blockIdx.z;

    const uint32_t* wbase = g_whf + (size_t)blockIdx.x*(16*2048);
    const uint32_t* bbase = g_xh2 + ((size_t)n*QTOT_ + (size_t)y0*QW_)*256; // +chunk*16

    // ldmatrix per-thread geometry: p selects nt pair {2p, 2p+1}
    // grp = lane>>3: bit1 -> nt within pair, bit0 -> k-half
    int qb[2], khalf_off;
    {
        int grp = lane >> 3, r = lane & 7;
        khalf_off = (grp & 1) * 16;            // byte offset for k-half
        #pragma unroll
        for (int p = 0; p < 2; p++) {
            int nt_g = p*2 + (grp >> 1);
            int px = warp_n*32 + nt_g*8 + r;
            qb[p] = ((px >> 6)*QW_ + (px & 63)) * B_ROWB;
        }
    }

    float acc[4][4][4];
    #pragma unroll
    for (int a = 0; a < 4; a++)
        #pragma unroll
        for (int b = 0; b < 4; b++)
            #pragma unroll
            for (int c = 0; c < 4; c++) acc[a][b][c] = 0.f;

    load_B_slab(sb + B_OFF, bbase, tid);
    load_A_tile(sb, wbase, tid);
    CP_COMMIT();

    int chunk = 0, k9 = 0;
    for (int j = 0; j < 144; j++) {
        int nk9 = k9 + 1, nchunk = chunk;
        if (nk9 == 9) { nk9 = 0; nchunk++; }
        if (j < 143)
            load_A_tile(sb + ((j+1)&1)*A_BYTES,
                        wbase + (size_t)nk9*(4*16*2048) + (size_t)nchunk*2048, tid);
        if (k9 == 0 && chunk + 1 < 16)
            load_B_slab(sb + B_OFF + ((chunk+1)&1)*B_BYTES,
                        bbase + (size_t)(chunk+1)*16, tid);
        CP_COMMIT();
        CP_WAIT1();
        __syncthreads();

        const uint4* As = (const uint4*)(smem + (j&1)*A_BYTES);
        const uint32_t Bbuf = sb + B_OFF + (chunk&1)*B_BYTES;
        const int kh = k9 / 3, kw = k9 % 3;
        const uint32_t sh = (uint32_t)((kh*QW_ + kw)*B_ROWB) + khalf_off;

        #pragma unroll
        for (int ks = 0; ks < 2; ks++) {
            uint4 af[4]; uint32_t bf[2][4];
            #pragma unroll
            for (int mt = 0; mt < 4; mt++)
                af[mt] = As[(ks*8 + warp_m*4 + mt)*32 + lane];
            #pragma unroll
            for (int p = 0; p < 2; p++)
                ldsm4(bf[p], Bbuf + (uint32_t)qb[p] + sh + ks*32);
            #pragma unroll
            for (int mt = 0; mt < 4; mt++)
                #pragma unroll
                for (int p = 0; p < 2; p++) {
                    mma_f16(acc[mt][p*2],   (const uint32_t*)&af[mt], bf[p]);     // nt=2p
                    mma_f16(acc[mt][p*2+1], (const uint32_t*)&af[mt], bf[p] + 2); // nt=2p+1
                }
        }
        __syncthreads();

        k9 = nk9; chunk = nchunk;
    }

    // ---- epilogue: demod, noise, LeakyReLU(0.2) ----
    const float nw = noise_w[0];
    #pragma unroll
    for (int mt = 0; mt < 4; mt++) {
        int co_a = co0 + warp_m*64 + mt*16 + g;
        float dm0 = g_demod[n*COUT_ + co_a];
        float dm1 = g_demod[n*COUT_ + co_a + 8];
        float* o0 = out + ((size_t)n*COUT_ + co_a)*HW_ + (size_t)y0*W_;
        float* o1 = o0 + (size_t)8*HW_;
        #pragma unroll
        for (int nt = 0; nt < 4; nt++) {
            int px0 = warp_n*32 + nt*8;
            int r = px0 >> 6;
            int c = (px0 & 63) + 2*t;
            const float* np = noise + ((size_t)n*H_ + y0 + r)*W_ + c;
            float n0 = np[0], n1 = np[1];
            float v0 = acc[mt][nt][0]*dm0 + nw*n0; v0 = fmaxf(v0, 0.2f*v0);
            float v1 = acc[mt][nt][1]*dm0 + nw*n1; v1 = fmaxf(v1, 0.2f*v1);
            float v2 = acc[mt][nt][2]*dm1 + nw*n0; v2 = fmaxf(v2, 0.2f*v2);
            float v3 = acc[mt][nt][3]*dm1 + nw*n1; v3 = fmaxf(v3, 0.2f*v3);
            *(float2*)(o0 + (size_t)r*W_ + c) = make_float2(v0, v1);
            *(float2*)(o1 + (size_t)r*W_ + c) = make_float2(v2, v3);
        }
    }
}

// ---------------------------------------------------------------------------
// Inputs: x, style, noise, weight, style_w, style_b, noise_weight
// ---------------------------------------------------------------------------
extern "C" void kernel_launch(void* const* d_in, const int* in_sizes, int n_in,
                              void* d_out, int out_size) {
    const float* x        = (const float*)d_in[0];
    const float* style    = (const float*)d_in[1];
    const float* noise    = (const float*)d_in[2];
    const float* weight   = (const float*)d_in[3];
    const float* style_w  = (const float*)d_in[4];
    const float* style_b  = (const float*)d_in[5];
    const float* noise_w  = (const float*)d_in[6];
    float* out = (float*)d_out;

    style_kernel<<<N_, STY_>>>(style, style_w, style_b);
    wsum2_kernel<<<(COUT_*CIN_)/256, 256>>>(weight);
    demod_kernel<<<dim3(N_, COUT_/64), 256>>>();
    pack_w_kernel<<<(9*COUT_*CIN_/2 + 255)/256, 256>>>(weight);
    zero_border_kernel<<<N_*QTOT_, 64>>>();
    pack_x_kernel<<<dim3(CIN_/64, H_, N_), 256>>>(x);

    cudaFuncSetAttribute(conv_mma_kernel,
                         cudaFuncAttributeMaxDynamicSharedMemorySize, SMEM_TOTAL);
    conv_mma_kernel<<<dim3(COUT_/128, H_/2, N_), 256, SMEM_TOTAL>>>(noise, noise_w, out);
}